// round 9
// baseline (speedup 1.0000x reference)
#include <cuda_runtime.h>
#include <cuda_bf16.h>
#include <math.h>
#include <stdint.h>

#define CB 16
#define CN 512
#define CD 256
#define CH 8
#define CDFF 1024
#define CL 2
#define NEG_INF_F (-1e9f)

// ---------------- scratch ----------------
static __device__ __align__(256) float g_x  [CB*CN*CD];
static __device__ __align__(256) float g_h  [CB*CN*CD];
static __device__ __align__(256) float g_qkv[CB*CN*768];
static __device__ __align__(256) float g_t  [CB*CN*CD];
static __device__ __align__(256) float g_ff [CB*CN*CDFF];
static __device__ __align__(256) float g_e1 [CB*CN];
static __device__ __align__(256) float g_e2 [CB*CN];
static __device__ __align__(256) float g_bias[CL*768];

static __device__ __align__(256) __nv_bfloat16 g_x3  [CB*CN*768];
static __device__ __align__(256) __nv_bfloat16 g_o3  [CB*CN*768];
static __device__ __align__(256) __nv_bfloat16 g_ff3 [CB*CN*3072];
static __device__ __align__(256) __nv_bfloat16 g_h3t [CB*CD*1536];
static __device__ __align__(256) __nv_bfloat16 g_al3 [CB*CN*1536];
static __device__ __align__(256) __nv_bfloat16 g_at3 [CB*CH*CN*1536];
static __device__ __align__(256) __nv_bfloat16 g_q3  [CB*CH*CN*128];
static __device__ __align__(256) __nv_bfloat16 g_k3  [CB*CH*CN*128];
static __device__ __align__(256) __nv_bfloat16 g_v3t [CB*CH*32*1536];
static __device__ __align__(256) __nv_bfloat16 g_wg3 [CD*768];
static __device__ __align__(256) __nv_bfloat16 g_wqkv3[CL*768*768];
static __device__ __align__(256) __nv_bfloat16 g_wo3 [CL*CD*768];
static __device__ __align__(256) __nv_bfloat16 g_w13 [CL*CDFF*768];
static __device__ __align__(256) __nv_bfloat16 g_w23 [CL*CD*3072];

__device__ __forceinline__ void bf_split_A(float v, __nv_bfloat16& a, __nv_bfloat16& b, __nv_bfloat16& c) {
    a = __float2bfloat16(v);
    b = __float2bfloat16(v - __bfloat162float(a));
    c = a;
}
__device__ __forceinline__ __nv_bfloat16 bf_lo(float v) {
    __nv_bfloat16 h = __float2bfloat16(v);
    return __float2bfloat16(v - __bfloat162float(h));
}
__device__ __forceinline__ void cpa16(uint32_t s, const void* g) {
    asm volatile("cp.async.cg.shared.global [%0], [%1], 16;" :: "r"(s), "l"(g));
}
__device__ __forceinline__ void ldsm4(uint32_t& r0, uint32_t& r1, uint32_t& r2, uint32_t& r3, uint32_t addr) {
    asm volatile("ldmatrix.sync.aligned.m8n8.x4.shared.b16 {%0,%1,%2,%3}, [%4];"
                 : "=r"(r0), "=r"(r1), "=r"(r2), "=r"(r3) : "r"(addr));
}

// ---------------- cp.async double-buffered mma.sync bf16 GEMM with ldmatrix ----------------
template<int BM, int TN, int WM, int WN>
__global__ __launch_bounds__(256)
void gemm_mma(const __nv_bfloat16* __restrict__ A, const __nv_bfloat16* __restrict__ B,
              const float* __restrict__ bias, float* __restrict__ C,
              int lda, int ldb, int ldc, int K3,
              long strA, long strB, long sC1, long sC2, int divC,
              float scale, int act,
              __nv_bfloat16* __restrict__ C3, long sC31, long sC32, int ldc3, int seg3)
{
    constexpr int BK = 64;
    constexpr int LDS = BK + 8;
    constexpr int MT = WM / 16;
    constexpr int NT = WN / 8;
    constexpr int WCOLS = TN / WN;
    constexpr int AITERS = BM / 32;
    constexpr int BITERS = TN / 32;

    extern __shared__ __nv_bfloat16 smem[];
    __nv_bfloat16* sA = smem;
    __nv_bfloat16* sB = smem + 2 * BM * LDS;

    const long z = blockIdx.z;
    A += z * strA;
    B += z * strB;
    C += (z / divC) * sC1 + (z % divC) * sC2;
    if (C3) C3 += (z / divC) * sC31 + (z % divC) * sC32;
    const int row0 = blockIdx.y * BM;
    const int col0 = blockIdx.x * TN;

    const int tid = threadIdx.x;
    const int w = tid >> 5, lane = tid & 31;
    const int wr = w / WCOLS, wc = w % WCOLS;
    const int gid = lane >> 2, tig = lane & 3;

    uint32_t sAu = (uint32_t)__cvta_generic_to_shared(sA);
    uint32_t sBu = (uint32_t)__cvta_generic_to_shared(sB);

    const int aRow = lane & 15, aCol = (lane >> 4) << 3;
    const int bRow = ((lane >> 4) << 3) + (lane & 7), bCol = ((lane >> 3) & 1) << 3;

    float acc[MT][NT][4];
#pragma unroll
    for (int mt = 0; mt < MT; mt++)
#pragma unroll
        for (int nt = 0; nt < NT; nt++)
#pragma unroll
            for (int i = 0; i < 4; i++) acc[mt][nt][i] = 0.f;

    const int nChunks = K3 / BK;

    auto issue = [&](int buf, int k0) {
#pragma unroll
        for (int i = 0; i < AITERS; i++) {
            const int idx = i * 256 + tid;
            const int r = idx >> 3, kc = (idx & 7) * 8;
            cpa16(sAu + (uint32_t)(((buf * BM + r) * LDS + kc) * 2),
                  A + (long)(row0 + r) * lda + k0 + kc);
        }
#pragma unroll
        for (int i = 0; i < BITERS; i++) {
            const int idx = i * 256 + tid;
            const int r = idx >> 3, kc = (idx & 7) * 8;
            cpa16(sBu + (uint32_t)(((buf * TN + r) * LDS + kc) * 2),
                  B + (long)(col0 + r) * ldb + k0 + kc);
        }
        asm volatile("cp.async.commit_group;");
    };

    issue(0, 0);
    for (int c = 0; c < nChunks; c++) {
        const int buf = c & 1;
        __syncthreads();
        if (c + 1 < nChunks) {
            issue(1 - buf, (c + 1) * BK);
            asm volatile("cp.async.wait_group 1;");
        } else {
            asm volatile("cp.async.wait_group 0;");
        }
        __syncthreads();

        const uint32_t aBase = sAu + (uint32_t)(buf * BM * LDS * 2);
        const uint32_t bBase = sBu + (uint32_t)(buf * TN * LDS * 2);
#pragma unroll
        for (int kk = 0; kk < BK; kk += 16) {
            uint32_t af[MT][4], bfr[NT][2];
#pragma unroll
            for (int mt = 0; mt < MT; mt++) {
                const int r = wr * WM + mt * 16;
                ldsm4(af[mt][0], af[mt][1], af[mt][2], af[mt][3],
                      aBase + (uint32_t)(((r + aRow) * LDS + kk + aCol) * 2));
            }
#pragma unroll
            for (int nt = 0; nt < NT; nt += 2) {
                const int n0 = wc * WN + nt * 8;
                ldsm4(bfr[nt][0], bfr[nt][1], bfr[nt + 1][0], bfr[nt + 1][1],
                      bBase + (uint32_t)(((n0 + bRow) * LDS + kk + bCol) * 2));
            }
#pragma unroll
            for (int mt = 0; mt < MT; mt++)
#pragma unroll
                for (int nt = 0; nt < NT; nt++) {
                    asm volatile(
                        "mma.sync.aligned.m16n8k16.row.col.f32.bf16.bf16.f32 "
                        "{%0,%1,%2,%3}, {%4,%5,%6,%7}, {%8,%9}, {%0,%1,%2,%3};"
                        : "+f"(acc[mt][nt][0]), "+f"(acc[mt][nt][1]),
                          "+f"(acc[mt][nt][2]), "+f"(acc[mt][nt][3])
                        : "r"(af[mt][0]), "r"(af[mt][1]), "r"(af[mt][2]), "r"(af[mt][3]),
                          "r"(bfr[nt][0]), "r"(bfr[nt][1]));
                }
        }
    }

    // epilogue
#pragma unroll
    for (int mt = 0; mt < MT; mt++) {
#pragma unroll
        for (int nt = 0; nt < NT; nt++) {
            const int rloc = wr * WM + mt * 16 + gid;
            const int cloc = wc * WN + nt * 8 + tig * 2;
            const int cg = col0 + cloc;
            float b0 = bias ? bias[cg] : 0.f;
            float b1 = bias ? bias[cg + 1] : 0.f;
#pragma unroll
            for (int half = 0; half < 2; half++) {
                const int rg = row0 + rloc + half * 8;
                float v0 = acc[mt][nt][half * 2 + 0] * scale + b0;
                float v1 = acc[mt][nt][half * 2 + 1] * scale + b1;
                if (act == 1) { v0 = fmaxf(v0, 0.f); v1 = fmaxf(v1, 0.f); }
                else if (act == 2) {
                    v0 = (v0 > 0.f) ? v0 : expm1f(v0);
                    v1 = (v1 > 0.f) ? v1 : expm1f(v1);
                }
                *reinterpret_cast<float2*>(&C[(long)rg * ldc + cg]) = make_float2(v0, v1);
                if (C3) {
                    __nv_bfloat16 h0 = __float2bfloat16(v0);
                    __nv_bfloat16 l0 = bf_lo(v0);
                    __nv_bfloat16 h1 = __float2bfloat16(v1);
                    __nv_bfloat16 l1 = bf_lo(v1);
                    long base = (long)rg * ldc3 + cg;
                    *reinterpret_cast<__nv_bfloat162*>(&C3[base]) = __nv_bfloat162(h0, h1);
                    *reinterpret_cast<__nv_bfloat162*>(&C3[base + seg3]) = __nv_bfloat162(l0, l1);
                    *reinterpret_cast<__nv_bfloat162*>(&C3[base + 2 * seg3]) = __nv_bfloat162(h0, h1);
                }
            }
        }
    }
}

// ---------------- fused weight split ----------------
struct WEnt { const float* src; __nv_bfloat16* dst; int R; int C; int tiles; };
struct WTab { WEnt e[13]; };

__global__ void wsplit_all(WTab tab)
{
    __shared__ float tile[128][33];
    int bid = blockIdx.x;
    int i = 0;
    while (bid >= tab.e[i].tiles) { bid -= tab.e[i].tiles; i++; }
    const float* in = tab.e[i].src;
    __nv_bfloat16* out = tab.e[i].dst;
    const int R = tab.e[i].R, C = tab.e[i].C;
    const int tC = C >> 5;
    const int r0 = (bid / tC) * 128, c0 = (bid % tC) * 32;

    for (int t = threadIdx.x; t < 128 * 32; t += 256) {
        int rr = t >> 5, cc = t & 31;
        tile[rr][cc] = in[(long)(r0 + rr) * C + c0 + cc];
    }
    __syncthreads();
    for (int t = threadIdx.x; t < 32 * 128; t += 256) {
        int cc = t >> 7, rr = t & 127;
        float v = tile[rr][cc];
        __nv_bfloat16 hi = __float2bfloat16(v);
        __nv_bfloat16 lo = bf_lo(v);
        long ob = (long)(c0 + cc) * (3L * R) + (r0 + rr);
        out[ob] = hi; out[ob + R] = hi; out[ob + 2L * R] = lo;
    }
}

__global__ void pack_bias(const float* __restrict__ bq, const float* __restrict__ bk,
                          const float* __restrict__ bv, float* __restrict__ dst)
{
    const int l = blockIdx.x;
    const int d = threadIdx.x;
    float v;
    if (d < 256) v = bq[l * 256 + d];
    else if (d < 512) v = bk[l * 256 + d - 256];
    else v = bv[l * 256 + d - 512];
    dst[l * 768 + d] = v;
}

// ---------------- elementwise kernels ----------------

__global__ void embed_kernel(const int* __restrict__ node, const float* __restrict__ embed,
                             float* __restrict__ x, __nv_bfloat16* __restrict__ x3)
{
    const int row = blockIdx.x;
    const int d = threadIdx.x;
    const float v = embed[(long)node[row] * CD + d];
    x[(long)row * CD + d] = v;
    __nv_bfloat16 h0, h1, h2;
    bf_split_A(v, h0, h1, h2);
    x3[(long)row * 768 + d] = h0;
    x3[(long)row * 768 + 256 + d] = h1;
    x3[(long)row * 768 + 512 + d] = h2;
}

__global__ void tsplitB(const float* __restrict__ in, __nv_bfloat16* __restrict__ out,
                        int irs, int R, long sIn1, long sIn2, int divIn, long sOut)
{
    __shared__ float tile[128][33];
    const long z = blockIdx.z;
    in  += (z / divIn) * sIn1 + (z % divIn) * sIn2;
    out += z * sOut;
    const int r0 = blockIdx.x * 128, c0 = blockIdx.y * 32;
    for (int i = threadIdx.x; i < 128 * 32; i += 256) {
        int rr = i >> 5, cc = i & 31;
        tile[rr][cc] = in[(long)(r0 + rr) * irs + c0 + cc];
    }
    __syncthreads();
    for (int i = threadIdx.x; i < 32 * 128; i += 256) {
        int cc = i >> 7, rr = i & 127;
        float v = tile[rr][cc];
        __nv_bfloat16 hi = __float2bfloat16(v);
        __nv_bfloat16 lo = bf_lo(v);
        long ob = (long)(c0 + cc) * (3L * R) + (r0 + rr);
        out[ob] = hi; out[ob + R] = hi; out[ob + 2L * R] = lo;
    }
}

__global__ void qk_split(const float* __restrict__ qkv,
                         __nv_bfloat16* __restrict__ q3, __nv_bfloat16* __restrict__ k3)
{
    const int row = blockIdx.x;
    const int b = row >> 9, i = row & 511;
    const int d = threadIdx.x;
    const int h = d >> 5, dd = d & 31;
    const long base = ((long)(b * CH + h) * CN + i) * 128;
    const __nv_bfloat16 zero = __float2bfloat16(0.f);
    float qv = qkv[(long)row * 768 + d];
    float kv = qkv[(long)row * 768 + 256 + d];
    __nv_bfloat16 qh = __float2bfloat16(qv);
    __nv_bfloat16 ql = bf_lo(qv);
    __nv_bfloat16 kh = __float2bfloat16(kv);
    __nv_bfloat16 kl = bf_lo(kv);
    q3[base + dd] = qh;  q3[base + 32 + dd] = ql; q3[base + 64 + dd] = qh; q3[base + 96 + dd] = zero;
    k3[base + dd] = kh;  k3[base + 32 + dd] = kh; k3[base + 64 + dd] = kl; k3[base + 96 + dd] = zero;
}

__global__ void e12_kernel(const float* __restrict__ h, const float* __restrict__ a1,
                           const float* __restrict__ a2, float* __restrict__ e1, float* __restrict__ e2)
{
    const int row = blockIdx.x;
    const int d = threadIdx.x;
    __shared__ float s1[256], s2[256];
    const float hv = h[(long)row * CD + d];
    s1[d] = hv * a1[d];
    s2[d] = hv * a2[d];
    __syncthreads();
    for (int off = 128; off > 0; off >>= 1) {
        if (d < off) { s1[d] += s1[d + off]; s2[d] += s2[d + off]; }
        __syncthreads();
    }
    if (d == 0) { e1[row] = s1[0]; e2[row] = s2[0]; }
}

__global__ void gat_softmax_kernel(const float* __restrict__ e1, const float* __restrict__ e2,
                                   const int* __restrict__ edge, __nv_bfloat16* __restrict__ al3)
{
    const int row = blockIdx.x;
    const int b = row / CN;
    const int t = threadIdx.x;
    __shared__ float red[256];
    const float ei = e1[row];
    float vals[2];
#pragma unroll
    for (int p = 0; p < 2; p++) {
        const int j = t + p * 256;
        float e = ei + e2[b * CN + j];
        e = (e >= 0.f) ? e : 0.2f * e;
        vals[p] = (edge[(long)row * CN + j] > 0) ? e : NEG_INF_F;
    }
    red[t] = fmaxf(vals[0], vals[1]);
    __syncthreads();
    for (int off = 128; off > 0; off >>= 1) { if (t < off) red[t] = fmaxf(red[t], red[t + off]); __syncthreads(); }
    const float m = red[0];
    __syncthreads();
    float ex[2] = {__expf(vals[0] - m), __expf(vals[1] - m)};
    red[t] = ex[0] + ex[1];
    __syncthreads();
    for (int off = 128; off > 0; off >>= 1) { if (t < off) red[t] += red[t + off]; __syncthreads(); }
    const float inv = 1.f / red[0];
    const long b3 = (long)row * 1536;
#pragma unroll
    for (int p = 0; p < 2; p++) {
        const int j = t + p * 256;
        __nv_bfloat16 h0, h1, h2;
        bf_split_A(ex[p] * inv, h0, h1, h2);
        al3[b3 + j] = h0; al3[b3 + 512 + j] = h1; al3[b3 + 1024 + j] = h2;
    }
}

__global__ void mha_softmax_kernel(float* __restrict__ s, const int* __restrict__ mask,
                                   __nv_bfloat16* __restrict__ at3)
{
    const int r = blockIdx.x;
    const int b = r / (CH * CN);
    const int t = threadIdx.x;
    __shared__ float red[256];
    float* srow = s + (long)r * CN;
    float vals[2];
#pragma unroll
    for (int p = 0; p < 2; p++) {
        const int j = t + p * 256;
        vals[p] = srow[j] + (float)mask[b * CN + j] * NEG_INF_F;
    }
    red[t] = fmaxf(vals[0], vals[1]);
    __syncthreads();
    for (int off = 128; off > 0; off >>= 1) { if (t < off) red[t] = fmaxf(red[t], red[t + off]); __syncthreads(); }
    const float m = red[0];
    __syncthreads();
    float ex[2] = {__expf(vals[0] - m), __expf(vals[1] - m)};
    red[t] = ex[0] + ex[1];
    __syncthreads();
    for (int off = 128; off > 0; off >>= 1) { if (t < off) red[t] += red[t + off]; __syncthreads(); }
    const float inv = 1.f / red[0];
    const long b3 = (long)r * 1536;
#pragma unroll
    for (int p = 0; p < 2; p++) {
        const int j = t + p * 256;
        const float pr = ex[p] * inv;
        srow[j] = pr;
        __nv_bfloat16 h0, h1, h2;
        bf_split_A(pr, h0, h1, h2);
        at3[b3 + j] = h0; at3[b3 + 512 + j] = h1; at3[b3 + 1024 + j] = h2;
    }
}

__global__ void scale_pe_kernel(float* __restrict__ x, __nv_bfloat16* __restrict__ x3)
{
    const int row = blockIdx.x;
    const int n = row % CN;
    const int d = threadIdx.x;
    const float expo = (2.0f * (float)(d >> 1)) / (float)CD;
    const float angle = (float)n * powf(10000.0f, -expo);
    const float pe = (d & 1) ? cosf(angle) : sinf(angle);
    const long idx = (long)row * CD + d;
    const float v = x[idx] * 16.0f + pe;
    x[idx] = v;
    __nv_bfloat16 h0, h1, h2;
    bf_split_A(v, h0, h1, h2);
    x3[(long)row * 768 + d] = h0;
    x3[(long)row * 768 + 256 + d] = h1;
    x3[(long)row * 768 + 512 + d] = h2;
}

__global__ void ln_kernel(const float* __restrict__ x, const float* __restrict__ delta,
                          const float* __restrict__ g, const float* __restrict__ bb,
                          float* __restrict__ out, __nv_bfloat16* __restrict__ x3)
{
    const int row = blockIdx.x;
    const int d = threadIdx.x;
    __shared__ float red[256];
    const long idx = (long)row * CD + d;
    const float v = x[idx] + delta[idx];
    red[d] = v;
    __syncthreads();
    for (int off = 128; off > 0; off >>= 1) { if (d < off) red[d] += red[d + off]; __syncthreads(); }
    const float mu = red[0] * (1.0f / CD);
    __syncthreads();
    const float c = v - mu;
    red[d] = c * c;
    __syncthreads();
    for (int off = 128; off > 0; off >>= 1) { if (d < off) red[d] += red[d + off]; __syncthreads(); }
    const float var = red[0] * (1.0f / CD);
    const float r = c * rsqrtf(var + 1e-6f) * g[d] + bb[d];
    out[idx] = r;
    if (x3) {
        __nv_bfloat16 h0, h1, h2;
        bf_split_A(r, h0, h1, h2);
        x3[(long)row * 768 + d] = h0;
        x3[(long)row * 768 + 256 + d] = h1;
        x3[(long)row * 768 + 512 + d] = h2;
    }
}

// ---------------- host ----------------
struct G3 { __nv_bfloat16* p; long s1; long s2; int ld; int seg; };

// cfg: 0 = (128,128,64,32), 1 = (128,32,32,16), 2 = (64,64,32,16), 3 = (64,128,32,32)
static void launch_gemm(const __nv_bfloat16* A, const __nv_bfloat16* B, const float* bias, float* C,
                        int M, int N, int K3, int lda, int ldb, int ldc,
                        long sA, long sB, long sC1, long sC2, int divC,
                        float scale, int act, int batch, int cfg, G3 g3)
{
    if (cfg == 0) {
        dim3 g(N / 128, M / 128, batch);
        size_t sm = (2 * 128 + 2 * 128) * 72 * 2;
        gemm_mma<128, 128, 64, 32><<<g, 256, sm>>>(A, B, bias, C, lda, ldb, ldc, K3,
            sA, sB, sC1, sC2, divC, scale, act, g3.p, g3.s1, g3.s2, g3.ld, g3.seg);
    } else if (cfg == 1) {
        dim3 g(N / 32, M / 128, batch);
        size_t sm = (2 * 128 + 2 * 32) * 72 * 2;
        gemm_mma<128, 32, 32, 16><<<g, 256, sm>>>(A, B, bias, C, lda, ldb, ldc, K3,
            sA, sB, sC1, sC2, divC, scale, act, g3.p, g3.s1, g3.s2, g3.ld, g3.seg);
    } else if (cfg == 2) {
        dim3 g(N / 64, M / 64, batch);
        size_t sm = (2 * 64 + 2 * 64) * 72 * 2;
        gemm_mma<64, 64, 32, 16><<<g, 256, sm>>>(A, B, bias, C, lda, ldb, ldc, K3,
            sA, sB, sC1, sC2, divC, scale, act, g3.p, g3.s1, g3.s2, g3.ld, g3.seg);
    } else {
        dim3 g(N / 128, M / 64, batch);
        size_t sm = (2 * 64 + 2 * 128) * 72 * 2;
        gemm_mma<64, 128, 32, 32><<<g, 256, sm>>>(A, B, bias, C, lda, ldb, ldc, K3,
            sA, sB, sC1, sC2, divC, scale, act, g3.p, g3.s1, g3.s2, g3.ld, g3.seg);
    }
}

extern "C" void kernel_launch(void* const* d_in, const int* in_sizes, int n_in,
                              void* d_out, int out_size)
{
    const int*   node  = (const int*)  d_in[0];
    const int*   edge  = (const int*)  d_in[1];
    const int*   mask  = (const int*)  d_in[2];
    const float* embed = (const float*)d_in[4];
    const float* Wg    = (const float*)d_in[5];
    const float* a1    = (const float*)d_in[6];
    const float* a2    = (const float*)d_in[7];
    const float* Wq    = (const float*)d_in[8];
    const float* bq    = (const float*)d_in[9];
    const float* Wk    = (const float*)d_in[10];
    const float* bk    = (const float*)d_in[11];
    const float* Wv    = (const float*)d_in[12];
    const float* bv    = (const float*)d_in[13];
    const float* Wo    = (const float*)d_in[14];
    const float* bo    = (const float*)d_in[15];
    const float* W1    = (const float*)d_in[16];
    const float* b1    = (const float*)d_in[17];
    const float* W2    = (const float*)d_in[18];
    const float* b2    = (const float*)d_in[19];
    const float* ln1g  = (const float*)d_in[20];
    const float* ln1b  = (const float*)d_in[21];
    const float* ln2g  = (const float*)d_in[22];
    const float* ln2b  = (const float*)d_in[23];

    cudaFuncSetAttribute((const void*)gemm_mma<128,128,64,32>, cudaFuncAttributeMaxDynamicSharedMemorySize, 75000);
    cudaFuncSetAttribute((const void*)gemm_mma<128,32,32,16>,  cudaFuncAttributeMaxDynamicSharedMemorySize, 50000);
    cudaFuncSetAttribute((const void*)gemm_mma<64,64,32,16>,   cudaFuncAttributeMaxDynamicSharedMemorySize, 40000);
    cudaFuncSetAttribute((const void*)gemm_mma<64,128,32,32>,  cudaFuncAttributeMaxDynamicSharedMemorySize, 60000);

    float *x, *h, *qkv, *t, *ff, *e1, *e2, *bias3;
    __nv_bfloat16 *x3, *o3, *ff3, *h3t, *al3, *at3, *q3, *k3, *v3t;
    __nv_bfloat16 *wg3, *wqkv3, *wo3, *w13, *w23;
    cudaGetSymbolAddress((void**)&x, g_x);     cudaGetSymbolAddress((void**)&h, g_h);
    cudaGetSymbolAddress((void**)&qkv, g_qkv); cudaGetSymbolAddress((void**)&t, g_t);
    cudaGetSymbolAddress((void**)&ff, g_ff);
    cudaGetSymbolAddress((void**)&e1, g_e1);   cudaGetSymbolAddress((void**)&e2, g_e2);
    cudaGetSymbolAddress((void**)&bias3, g_bias);
    cudaGetSymbolAddress((void**)&x3, g_x3);   cudaGetSymbolAddress((void**)&o3, g_o3);
    cudaGetSymbolAddress((void**)&ff3, g_ff3); cudaGetSymbolAddress((void**)&h3t, g_h3t);
    cudaGetSymbolAddress((void**)&al3, g_al3); cudaGetSymbolAddress((void**)&at3, g_at3);
    cudaGetSymbolAddress((void**)&q3, g_q3);   cudaGetSymbolAddress((void**)&k3, g_k3);
    cudaGetSymbolAddress((void**)&v3t, g_v3t);
    cudaGetSymbolAddress((void**)&wg3, g_wg3); cudaGetSymbolAddress((void**)&wqkv3, g_wqkv3);
    cudaGetSymbolAddress((void**)&wo3, g_wo3); cudaGetSymbolAddress((void**)&w13, g_w13);
    cudaGetSymbolAddress((void**)&w23, g_w23);

    float* out_x    = (float*)d_out;
    float* out_attn = (float*)d_out + (long)CB * CN * CD;

    const int M = CB * CN;
    const long ND = (long)CN * CD;
    const float inv_sqrt_dh = 0.17677669529663687f;
    const G3 no3 = {nullptr, 0, 0, 0, 0};

    WTab tab;
    int nTiles = 0;
    auto add = [&](int i, const float* src, __nv_bfloat16* dst, int R, int C) {
        tab.e[i] = {src, dst, R, C, (R / 128) * (C / 32)};
        nTiles += tab.e[i].tiles;
    };
    add(0, Wg, wg3, 256, 256);
    for (int l = 0; l < CL; l++) {
        const long w256 = (long)l * 65536, w1k = (long)l * 262144;
        add(1 + l * 6, Wq + w256, wqkv3 + (long)l * 768 * 768, 256, 256);
        add(2 + l * 6, Wk + w256, wqkv3 + (long)l * 768 * 768 + 256 * 768, 256, 256);
        add(3 + l * 6, Wv + w256, wqkv3 + (long)l * 768 * 768 + 512 * 768, 256, 256);
        add(4 + l * 6, Wo + w256, wo3 + (long)l * 256 * 768, 256, 256);
        add(5 + l * 6, W1 + w1k, w13 + (long)l * 1024 * 768, 256, 1024);
        add(6 + l * 6, W2 + w1k, w23 + (long)l * 256 * 3072, 1024, 256);
    }
    wsplit_all<<<nTiles, 256>>>(tab);
    pack_bias<<<CL, 768>>>(bq, bk, bv, bias3);

    embed_kernel<<<M, CD>>>(node, embed, x, x3);

    for (int hop = 0; hop < 2; hop++) {
        launch_gemm(x3, wg3, nullptr, h, M, CD, 768, 768, 768, CD,
                    0, 0, 0, 0, 1, 1.f, 0, 1, 2, no3);
        tsplitB<<<dim3(4, 8, CB), 256>>>(h, h3t, CD, CN, ND, 0, 1, (long)CD * 1536);
        e12_kernel<<<M, CD>>>(h, a1, a2, e1, e2);
        gat_softmax_kernel<<<M, 256>>>(e1, e2, edge, al3);
        G3 gx3 = {x3, (long)CN * 768, 0, 768, 256};
        launch_gemm(al3, h3t, nullptr, x, CN, CD, 1536, 1536, 1536, CD,
                    (long)CN * 1536, (long)CD * 1536, ND, 0, 1, 1.f, 2, CB, 2, gx3);
    }

    scale_pe_kernel<<<M, CD>>>(x, x3);

    for (int l = 0; l < CL; l++) {
        launch_gemm(x3, wqkv3 + (long)l * 768 * 768, bias3 + l * 768, qkv,
                    M, 768, 768, 768, 768, 768,
                    0, 0, 0, 0, 1, 1.f, 0, 1, 3, no3);

        qk_split<<<M, 256>>>(qkv, q3, k3);
        tsplitB<<<dim3(4, 1, CB * CH), 256>>>(qkv + 512, v3t, 768, CN,
                                              (long)CN * 768, 32, CH, 32L * 1536);

        launch_gemm(q3, k3, nullptr, out_attn, CN, CN, 128, 128, 128, CN,
                    (long)CN * 128, (long)CN * 128, (long)CN * CN, 0, 1,
                    inv_sqrt_dh, 0, CB * CH, 0, no3);

        mha_softmax_kernel<<<CB * CH * CN, 256>>>(out_attn, mask, at3);

        G3 go3 = {o3, (long)CN * 768, 32, 768, 256};
        launch_gemm(at3, v3t, nullptr, t, CN, 32, 1536, 1536, 1536, CD,
                    (long)CN * 1536, 32L * 1536, ND, 32, CH, 1.f, 0, CB * CH, 1, go3);

        launch_gemm(o3, wo3 + (long)l * 256 * 768, bo + l * CD, t, M, CD, 768, 768, 768, CD,
                    0, 0, 0, 0, 1, 1.f, 0, 1, 2, no3);
        ln_kernel<<<M, CD>>>(x, t, ln1g + l * CD, ln1b + l * CD, x, x3);

        G3 gff3 = {ff3, 0, 0, 3072, 1024};
        launch_gemm(x3, w13 + (long)l * 1024 * 768, b1 + l * CDFF, ff, M, CDFF, 768, 768, 768, CDFF,
                    0, 0, 0, 0, 1, 1.f, 1, 1, 0, gff3);
        launch_gemm(ff3, w23 + (long)l * 256 * 3072, b2 + l * CD, t, M, CD, 3072, 3072, 3072, CD,
                    0, 0, 0, 0, 1, 1.f, 0, 1, 2, no3);
        const bool last = (l == CL - 1);
        ln_kernel<<<M, CD>>>(x, t, ln2g + l * CD, ln2b + l * CD,
                             last ? out_x : x, last ? nullptr : x3);
    }
}

// round 10
// speedup vs baseline: 1.0476x; 1.0476x over previous
#include <cuda_runtime.h>
#include <cuda_bf16.h>
#include <math.h>
#include <stdint.h>

#define CB 16
#define CN 512
#define CD 256
#define CH 8
#define CDFF 1024
#define CL 2
#define NEG_INF_F (-1e9f)

// ---------------- scratch ----------------
static __device__ __align__(256) float g_x  [CB*CN*CD];
static __device__ __align__(256) float g_h  [CB*CN*CD];
static __device__ __align__(256) float g_qkv[CB*CN*768];
static __device__ __align__(256) float g_t  [CB*CN*CD];
static __device__ __align__(256) float g_ff [CB*CN*CDFF];
static __device__ __align__(256) float g_e1 [CB*CN];
static __device__ __align__(256) float g_e2 [CB*CN];
static __device__ __align__(256) float g_bias[CL*768];

static __device__ __align__(256) __nv_bfloat16 g_x3  [CB*CN*768];
static __device__ __align__(256) __nv_bfloat16 g_o3  [CB*CN*768];
static __device__ __align__(256) __nv_bfloat16 g_ff3 [CB*CN*3072];
static __device__ __align__(256) __nv_bfloat16 g_h3t [CB*CD*1536];
static __device__ __align__(256) __nv_bfloat16 g_al3 [CB*CN*1536];
static __device__ __align__(256) __nv_bfloat16 g_at3 [CB*CH*CN*1536];
static __device__ __align__(256) __nv_bfloat16 g_q3  [CB*CH*CN*128];
static __device__ __align__(256) __nv_bfloat16 g_k3  [CB*CH*CN*128];
static __device__ __align__(256) __nv_bfloat16 g_v3t [CB*CH*32*1536];
static __device__ __align__(256) __nv_bfloat16 g_wg3 [CD*768];
static __device__ __align__(256) __nv_bfloat16 g_wqkv3[CL*768*768];
static __device__ __align__(256) __nv_bfloat16 g_wo3 [CL*CD*768];
static __device__ __align__(256) __nv_bfloat16 g_w13 [CL*CDFF*768];
static __device__ __align__(256) __nv_bfloat16 g_w23 [CL*CD*3072];

__device__ __forceinline__ void bf_split_A(float v, __nv_bfloat16& a, __nv_bfloat16& b, __nv_bfloat16& c) {
    a = __float2bfloat16(v);
    b = __float2bfloat16(v - __bfloat162float(a));
    c = a;
}
__device__ __forceinline__ __nv_bfloat16 bf_lo(float v) {
    __nv_bfloat16 h = __float2bfloat16(v);
    return __float2bfloat16(v - __bfloat162float(h));
}
__device__ __forceinline__ void cpa16(uint32_t s, const void* g) {
    asm volatile("cp.async.cg.shared.global [%0], [%1], 16;" :: "r"(s), "l"(g));
}
__device__ __forceinline__ void ldsm4(uint32_t& r0, uint32_t& r1, uint32_t& r2, uint32_t& r3, uint32_t addr) {
    asm volatile("ldmatrix.sync.aligned.m8n8.x4.shared.b16 {%0,%1,%2,%3}, [%4];"
                 : "=r"(r0), "=r"(r1), "=r"(r2), "=r"(r3) : "r"(addr));
}

// ---------------- 3-stage cp.async mma.sync bf16 GEMM with ldmatrix ----------------
// Warp tile fixed at 32x32 (MT=2,NT=4: 2 A-ldsm + 2 B-ldsm per 8 MMAs).
template<int BM, int TN>
__global__ __launch_bounds__((BM/32)*(TN/32)*32)
void gemm_mma(const __nv_bfloat16* __restrict__ A, const __nv_bfloat16* __restrict__ B,
              const float* __restrict__ bias, float* __restrict__ C,
              int lda, int ldb, int ldc, int K3,
              long strA, long strB, long sC1, long sC2, int divC,
              float scale, int act,
              __nv_bfloat16* __restrict__ C3, long sC31, long sC32, int ldc3, int seg3)
{
    constexpr int WM = 32, WN = 32;
    constexpr int BK = 64;
    constexpr int LDS = BK + 8;
    constexpr int MT = WM / 16;       // 2
    constexpr int NT = WN / 8;        // 4
    constexpr int WCOLS = TN / WN;
    constexpr int THREADS = (BM / WM) * (TN / WN) * 32;
    constexpr int AITERS = BM * 8 / THREADS;
    constexpr int BITERS = TN * 8 / THREADS;
    constexpr int STAGES = 3;

    extern __shared__ __nv_bfloat16 smem[];
    __nv_bfloat16* sA = smem;
    __nv_bfloat16* sB = smem + STAGES * BM * LDS;

    const long z = blockIdx.z;
    A += z * strA;
    B += z * strB;
    C += (z / divC) * sC1 + (z % divC) * sC2;
    if (C3) C3 += (z / divC) * sC31 + (z % divC) * sC32;
    const int row0 = blockIdx.y * BM;
    const int col0 = blockIdx.x * TN;

    const int tid = threadIdx.x;
    const int w = tid >> 5, lane = tid & 31;
    const int wr = w / WCOLS, wc = w % WCOLS;
    const int gid = lane >> 2, tig = lane & 3;

    uint32_t sAu = (uint32_t)__cvta_generic_to_shared(sA);
    uint32_t sBu = (uint32_t)__cvta_generic_to_shared(sB);

    const int aRow = lane & 15, aCol = (lane >> 4) << 3;
    const int bRow = ((lane >> 4) << 3) + (lane & 7), bCol = ((lane >> 3) & 1) << 3;

    float acc[MT][NT][4];
#pragma unroll
    for (int mt = 0; mt < MT; mt++)
#pragma unroll
        for (int nt = 0; nt < NT; nt++)
#pragma unroll
            for (int i = 0; i < 4; i++) acc[mt][nt][i] = 0.f;

    const int nChunks = K3 / BK;

    auto issue = [&](int s) {
        const int buf = s % STAGES;
        const int k0 = s * BK;
#pragma unroll
        for (int i = 0; i < AITERS; i++) {
            const int idx = i * THREADS + tid;
            const int r = idx >> 3, kc = (idx & 7) * 8;
            cpa16(sAu + (uint32_t)(((buf * BM + r) * LDS + kc) * 2),
                  A + (long)(row0 + r) * lda + k0 + kc);
        }
#pragma unroll
        for (int i = 0; i < BITERS; i++) {
            const int idx = i * THREADS + tid;
            const int r = idx >> 3, kc = (idx & 7) * 8;
            cpa16(sBu + (uint32_t)(((buf * TN + r) * LDS + kc) * 2),
                  B + (long)(col0 + r) * ldb + k0 + kc);
        }
        asm volatile("cp.async.commit_group;");
    };

    issue(0);
    if (nChunks > 1) issue(1);
    for (int c = 0; c < nChunks; c++) {
        if (c + 2 < nChunks) issue(c + 2);
        const int rem = nChunks - 1 - c;
        if (rem >= 2)      asm volatile("cp.async.wait_group 2;");
        else if (rem == 1) asm volatile("cp.async.wait_group 1;");
        else               asm volatile("cp.async.wait_group 0;");
        __syncthreads();

        const int buf = c % STAGES;
        const uint32_t aBase = sAu + (uint32_t)(buf * BM * LDS * 2);
        const uint32_t bBase = sBu + (uint32_t)(buf * TN * LDS * 2);
#pragma unroll
        for (int kk = 0; kk < BK; kk += 16) {
            uint32_t af[MT][4], bfr[NT][2];
#pragma unroll
            for (int mt = 0; mt < MT; mt++) {
                const int r = wr * WM + mt * 16;
                ldsm4(af[mt][0], af[mt][1], af[mt][2], af[mt][3],
                      aBase + (uint32_t)(((r + aRow) * LDS + kk + aCol) * 2));
            }
#pragma unroll
            for (int nt = 0; nt < NT; nt += 2) {
                const int n0 = wc * WN + nt * 8;
                ldsm4(bfr[nt][0], bfr[nt][1], bfr[nt + 1][0], bfr[nt + 1][1],
                      bBase + (uint32_t)(((n0 + bRow) * LDS + kk + bCol) * 2));
            }
#pragma unroll
            for (int mt = 0; mt < MT; mt++)
#pragma unroll
                for (int nt = 0; nt < NT; nt++) {
                    asm volatile(
                        "mma.sync.aligned.m16n8k16.row.col.f32.bf16.bf16.f32 "
                        "{%0,%1,%2,%3}, {%4,%5,%6,%7}, {%8,%9}, {%0,%1,%2,%3};"
                        : "+f"(acc[mt][nt][0]), "+f"(acc[mt][nt][1]),
                          "+f"(acc[mt][nt][2]), "+f"(acc[mt][nt][3])
                        : "r"(af[mt][0]), "r"(af[mt][1]), "r"(af[mt][2]), "r"(af[mt][3]),
                          "r"(bfr[nt][0]), "r"(bfr[nt][1]));
                }
        }
        __syncthreads();
    }

    // epilogue
#pragma unroll
    for (int mt = 0; mt < MT; mt++) {
#pragma unroll
        for (int nt = 0; nt < NT; nt++) {
            const int rloc = wr * WM + mt * 16 + gid;
            const int cloc = wc * WN + nt * 8 + tig * 2;
            const int cg = col0 + cloc;
            float b0 = bias ? bias[cg] : 0.f;
            float b1 = bias ? bias[cg + 1] : 0.f;
#pragma unroll
            for (int half = 0; half < 2; half++) {
                const int rg = row0 + rloc + half * 8;
                float v0 = acc[mt][nt][half * 2 + 0] * scale + b0;
                float v1 = acc[mt][nt][half * 2 + 1] * scale + b1;
                if (act == 1) { v0 = fmaxf(v0, 0.f); v1 = fmaxf(v1, 0.f); }
                else if (act == 2) {
                    v0 = (v0 > 0.f) ? v0 : expm1f(v0);
                    v1 = (v1 > 0.f) ? v1 : expm1f(v1);
                }
                *reinterpret_cast<float2*>(&C[(long)rg * ldc + cg]) = make_float2(v0, v1);
                if (C3) {
                    __nv_bfloat16 h0 = __float2bfloat16(v0);
                    __nv_bfloat16 l0 = bf_lo(v0);
                    __nv_bfloat16 h1 = __float2bfloat16(v1);
                    __nv_bfloat16 l1 = bf_lo(v1);
                    long base = (long)rg * ldc3 + cg;
                    *reinterpret_cast<__nv_bfloat162*>(&C3[base]) = __nv_bfloat162(h0, h1);
                    *reinterpret_cast<__nv_bfloat162*>(&C3[base + seg3]) = __nv_bfloat162(l0, l1);
                    *reinterpret_cast<__nv_bfloat162*>(&C3[base + 2 * seg3]) = __nv_bfloat162(h0, h1);
                }
            }
        }
    }
}

// ---------------- fused weight split ----------------
struct WEnt { const float* src; __nv_bfloat16* dst; int R; int C; int tiles; };
struct WTab { WEnt e[13]; };

__global__ void wsplit_all(WTab tab)
{
    __shared__ float tile[128][33];
    int bid = blockIdx.x;
    int i = 0;
    while (bid >= tab.e[i].tiles) { bid -= tab.e[i].tiles; i++; }
    const float* in = tab.e[i].src;
    __nv_bfloat16* out = tab.e[i].dst;
    const int R = tab.e[i].R, C = tab.e[i].C;
    const int tC = C >> 5;
    const int r0 = (bid / tC) * 128, c0 = (bid % tC) * 32;

    for (int t = threadIdx.x; t < 128 * 32; t += 256) {
        int rr = t >> 5, cc = t & 31;
        tile[rr][cc] = in[(long)(r0 + rr) * C + c0 + cc];
    }
    __syncthreads();
    for (int t = threadIdx.x; t < 32 * 128; t += 256) {
        int cc = t >> 7, rr = t & 127;
        float v = tile[rr][cc];
        __nv_bfloat16 hi = __float2bfloat16(v);
        __nv_bfloat16 lo = bf_lo(v);
        long ob = (long)(c0 + cc) * (3L * R) + (r0 + rr);
        out[ob] = hi; out[ob + R] = hi; out[ob + 2L * R] = lo;
    }
}

__global__ void pack_bias(const float* __restrict__ bq, const float* __restrict__ bk,
                          const float* __restrict__ bv, float* __restrict__ dst)
{
    const int l = blockIdx.x;
    const int d = threadIdx.x;
    float v;
    if (d < 256) v = bq[l * 256 + d];
    else if (d < 512) v = bk[l * 256 + d - 256];
    else v = bv[l * 256 + d - 512];
    dst[l * 768 + d] = v;
}

// ---------------- elementwise kernels ----------------

__global__ void embed_kernel(const int* __restrict__ node, const float* __restrict__ embed,
                             float* __restrict__ x, __nv_bfloat16* __restrict__ x3)
{
    const int row = blockIdx.x;
    const int d = threadIdx.x;
    const float v = embed[(long)node[row] * CD + d];
    x[(long)row * CD + d] = v;
    __nv_bfloat16 h0, h1, h2;
    bf_split_A(v, h0, h1, h2);
    x3[(long)row * 768 + d] = h0;
    x3[(long)row * 768 + 256 + d] = h1;
    x3[(long)row * 768 + 512 + d] = h2;
}

__global__ void tsplitB(const float* __restrict__ in, __nv_bfloat16* __restrict__ out,
                        int irs, int R, long sIn1, long sIn2, int divIn, long sOut)
{
    __shared__ float tile[128][33];
    const long z = blockIdx.z;
    in  += (z / divIn) * sIn1 + (z % divIn) * sIn2;
    out += z * sOut;
    const int r0 = blockIdx.x * 128, c0 = blockIdx.y * 32;
    for (int i = threadIdx.x; i < 128 * 32; i += 256) {
        int rr = i >> 5, cc = i & 31;
        tile[rr][cc] = in[(long)(r0 + rr) * irs + c0 + cc];
    }
    __syncthreads();
    for (int i = threadIdx.x; i < 32 * 128; i += 256) {
        int cc = i >> 7, rr = i & 127;
        float v = tile[rr][cc];
        __nv_bfloat16 hi = __float2bfloat16(v);
        __nv_bfloat16 lo = bf_lo(v);
        long ob = (long)(c0 + cc) * (3L * R) + (r0 + rr);
        out[ob] = hi; out[ob + R] = hi; out[ob + 2L * R] = lo;
    }
}

__global__ void qk_split(const float* __restrict__ qkv,
                         __nv_bfloat16* __restrict__ q3, __nv_bfloat16* __restrict__ k3)
{
    const int row = blockIdx.x;
    const int b = row >> 9, i = row & 511;
    const int d = threadIdx.x;
    const int h = d >> 5, dd = d & 31;
    const long base = ((long)(b * CH + h) * CN + i) * 128;
    const __nv_bfloat16 zero = __float2bfloat16(0.f);
    float qv = qkv[(long)row * 768 + d];
    float kv = qkv[(long)row * 768 + 256 + d];
    __nv_bfloat16 qh = __float2bfloat16(qv);
    __nv_bfloat16 ql = bf_lo(qv);
    __nv_bfloat16 kh = __float2bfloat16(kv);
    __nv_bfloat16 kl = bf_lo(kv);
    q3[base + dd] = qh;  q3[base + 32 + dd] = ql; q3[base + 64 + dd] = qh; q3[base + 96 + dd] = zero;
    k3[base + dd] = kh;  k3[base + 32 + dd] = kh; k3[base + 64 + dd] = kl; k3[base + 96 + dd] = zero;
}

__global__ void e12_kernel(const float* __restrict__ h, const float* __restrict__ a1,
                           const float* __restrict__ a2, float* __restrict__ e1, float* __restrict__ e2)
{
    const int row = blockIdx.x;
    const int d = threadIdx.x;
    __shared__ float s1[256], s2[256];
    const float hv = h[(long)row * CD + d];
    s1[d] = hv * a1[d];
    s2[d] = hv * a2[d];
    __syncthreads();
    for (int off = 128; off > 0; off >>= 1) {
        if (d < off) { s1[d] += s1[d + off]; s2[d] += s2[d + off]; }
        __syncthreads();
    }
    if (d == 0) { e1[row] = s1[0]; e2[row] = s2[0]; }
}

__global__ void gat_softmax_kernel(const float* __restrict__ e1, const float* __restrict__ e2,
                                   const int* __restrict__ edge, __nv_bfloat16* __restrict__ al3)
{
    const int row = blockIdx.x;
    const int b = row / CN;
    const int t = threadIdx.x;
    __shared__ float red[256];
    const float ei = e1[row];
    float vals[2];
#pragma unroll
    for (int p = 0; p < 2; p++) {
        const int j = t + p * 256;
        float e = ei + e2[b * CN + j];
        e = (e >= 0.f) ? e : 0.2f * e;
        vals[p] = (edge[(long)row * CN + j] > 0) ? e : NEG_INF_F;
    }
    red[t] = fmaxf(vals[0], vals[1]);
    __syncthreads();
    for (int off = 128; off > 0; off >>= 1) { if (t < off) red[t] = fmaxf(red[t], red[t + off]); __syncthreads(); }
    const float m = red[0];
    __syncthreads();
    float ex[2] = {__expf(vals[0] - m), __expf(vals[1] - m)};
    red[t] = ex[0] + ex[1];
    __syncthreads();
    for (int off = 128; off > 0; off >>= 1) { if (t < off) red[t] += red[t + off]; __syncthreads(); }
    const float inv = 1.f / red[0];
    const long b3 = (long)row * 1536;
#pragma unroll
    for (int p = 0; p < 2; p++) {
        const int j = t + p * 256;
        __nv_bfloat16 h0, h1, h2;
        bf_split_A(ex[p] * inv, h0, h1, h2);
        al3[b3 + j] = h0; al3[b3 + 512 + j] = h1; al3[b3 + 1024 + j] = h2;
    }
}

__global__ void mha_softmax_kernel(float* __restrict__ s, const int* __restrict__ mask,
                                   __nv_bfloat16* __restrict__ at3)
{
    const int r = blockIdx.x;
    const int b = r / (CH * CN);
    const int t = threadIdx.x;
    __shared__ float red[256];
    float* srow = s + (long)r * CN;
    float vals[2];
#pragma unroll
    for (int p = 0; p < 2; p++) {
        const int j = t + p * 256;
        vals[p] = srow[j] + (float)mask[b * CN + j] * NEG_INF_F;
    }
    red[t] = fmaxf(vals[0], vals[1]);
    __syncthreads();
    for (int off = 128; off > 0; off >>= 1) { if (t < off) red[t] = fmaxf(red[t], red[t + off]); __syncthreads(); }
    const float m = red[0];
    __syncthreads();
    float ex[2] = {__expf(vals[0] - m), __expf(vals[1] - m)};
    red[t] = ex[0] + ex[1];
    __syncthreads();
    for (int off = 128; off > 0; off >>= 1) { if (t < off) red[t] += red[t + off]; __syncthreads(); }
    const float inv = 1.f / red[0];
    const long b3 = (long)r * 1536;
#pragma unroll
    for (int p = 0; p < 2; p++) {
        const int j = t + p * 256;
        const float pr = ex[p] * inv;
        srow[j] = pr;
        __nv_bfloat16 h0, h1, h2;
        bf_split_A(pr, h0, h1, h2);
        at3[b3 + j] = h0; at3[b3 + 512 + j] = h1; at3[b3 + 1024 + j] = h2;
    }
}

__global__ void scale_pe_kernel(float* __restrict__ x, __nv_bfloat16* __restrict__ x3)
{
    const int row = blockIdx.x;
    const int n = row % CN;
    const int d = threadIdx.x;
    const float expo = (2.0f * (float)(d >> 1)) / (float)CD;
    const float angle = (float)n * powf(10000.0f, -expo);
    const float pe = (d & 1) ? cosf(angle) : sinf(angle);
    const long idx = (long)row * CD + d;
    const float v = x[idx] * 16.0f + pe;
    x[idx] = v;
    __nv_bfloat16 h0, h1, h2;
    bf_split_A(v, h0, h1, h2);
    x3[(long)row * 768 + d] = h0;
    x3[(long)row * 768 + 256 + d] = h1;
    x3[(long)row * 768 + 512 + d] = h2;
}

__global__ void ln_kernel(const float* __restrict__ x, const float* __restrict__ delta,
                          const float* __restrict__ g, const float* __restrict__ bb,
                          float* __restrict__ out, __nv_bfloat16* __restrict__ x3)
{
    const int row = blockIdx.x;
    const int d = threadIdx.x;
    __shared__ float red[256];
    const long idx = (long)row * CD + d;
    const float v = x[idx] + delta[idx];
    red[d] = v;
    __syncthreads();
    for (int off = 128; off > 0; off >>= 1) { if (d < off) red[d] += red[d + off]; __syncthreads(); }
    const float mu = red[0] * (1.0f / CD);
    __syncthreads();
    const float c = v - mu;
    red[d] = c * c;
    __syncthreads();
    for (int off = 128; off > 0; off >>= 1) { if (d < off) red[d] += red[d + off]; __syncthreads(); }
    const float var = red[0] * (1.0f / CD);
    const float r = c * rsqrtf(var + 1e-6f) * g[d] + bb[d];
    out[idx] = r;
    if (x3) {
        __nv_bfloat16 h0, h1, h2;
        bf_split_A(r, h0, h1, h2);
        x3[(long)row * 768 + d] = h0;
        x3[(long)row * 768 + 256 + d] = h1;
        x3[(long)row * 768 + 512 + d] = h2;
    }
}

// ---------------- host ----------------
struct G3 { __nv_bfloat16* p; long s1; long s2; int ld; int seg; };

// cfg 0: BM=64 TN=64 (128 thr); cfg 1: BM=64 TN=32 (64 thr)
static void launch_gemm(const __nv_bfloat16* A, const __nv_bfloat16* B, const float* bias, float* C,
                        int M, int N, int K3, int lda, int ldb, int ldc,
                        long sA, long sB, long sC1, long sC2, int divC,
                        float scale, int act, int batch, int cfg, G3 g3)
{
    if (cfg == 0) {
        dim3 g(N / 64, M / 64, batch);
        size_t sm = 3 * (64 + 64) * 72 * 2;
        gemm_mma<64, 64><<<g, 128, sm>>>(A, B, bias, C, lda, ldb, ldc, K3,
            sA, sB, sC1, sC2, divC, scale, act, g3.p, g3.s1, g3.s2, g3.ld, g3.seg);
    } else {
        dim3 g(N / 32, M / 64, batch);
        size_t sm = 3 * (64 + 32) * 72 * 2;
        gemm_mma<64, 32><<<g, 64, sm>>>(A, B, bias, C, lda, ldb, ldc, K3,
            sA, sB, sC1, sC2, divC, scale, act, g3.p, g3.s1, g3.s2, g3.ld, g3.seg);
    }
}

extern "C" void kernel_launch(void* const* d_in, const int* in_sizes, int n_in,
                              void* d_out, int out_size)
{
    const int*   node  = (const int*)  d_in[0];
    const int*   edge  = (const int*)  d_in[1];
    const int*   mask  = (const int*)  d_in[2];
    const float* embed = (const float*)d_in[4];
    const float* Wg    = (const float*)d_in[5];
    const float* a1    = (const float*)d_in[6];
    const float* a2    = (const float*)d_in[7];
    const float* Wq    = (const float*)d_in[8];
    const float* bq    = (const float*)d_in[9];
    const float* Wk    = (const float*)d_in[10];
    const float* bk    = (const float*)d_in[11];
    const float* Wv    = (const float*)d_in[12];
    const float* bv    = (const float*)d_in[13];
    const float* Wo    = (const float*)d_in[14];
    const float* bo    = (const float*)d_in[15];
    const float* W1    = (const float*)d_in[16];
    const float* b1    = (const float*)d_in[17];
    const float* W2    = (const float*)d_in[18];
    const float* b2    = (const float*)d_in[19];
    const float* ln1g  = (const float*)d_in[20];
    const float* ln1b  = (const float*)d_in[21];
    const float* ln2g  = (const float*)d_in[22];
    const float* ln2b  = (const float*)d_in[23];

    cudaFuncSetAttribute((const void*)gemm_mma<64,64>, cudaFuncAttributeMaxDynamicSharedMemorySize, 60000);
    cudaFuncSetAttribute((const void*)gemm_mma<64,32>, cudaFuncAttributeMaxDynamicSharedMemorySize, 45000);

    float *x, *h, *qkv, *t, *ff, *e1, *e2, *bias3;
    __nv_bfloat16 *x3, *o3, *ff3, *h3t, *al3, *at3, *q3, *k3, *v3t;
    __nv_bfloat16 *wg3, *wqkv3, *wo3, *w13, *w23;
    cudaGetSymbolAddress((void**)&x, g_x);     cudaGetSymbolAddress((void**)&h, g_h);
    cudaGetSymbolAddress((void**)&qkv, g_qkv); cudaGetSymbolAddress((void**)&t, g_t);
    cudaGetSymbolAddress((void**)&ff, g_ff);
    cudaGetSymbolAddress((void**)&e1, g_e1);   cudaGetSymbolAddress((void**)&e2, g_e2);
    cudaGetSymbolAddress((void**)&bias3, g_bias);
    cudaGetSymbolAddress((void**)&x3, g_x3);   cudaGetSymbolAddress((void**)&o3, g_o3);
    cudaGetSymbolAddress((void**)&ff3, g_ff3); cudaGetSymbolAddress((void**)&h3t, g_h3t);
    cudaGetSymbolAddress((void**)&al3, g_al3); cudaGetSymbolAddress((void**)&at3, g_at3);
    cudaGetSymbolAddress((void**)&q3, g_q3);   cudaGetSymbolAddress((void**)&k3, g_k3);
    cudaGetSymbolAddress((void**)&v3t, g_v3t);
    cudaGetSymbolAddress((void**)&wg3, g_wg3); cudaGetSymbolAddress((void**)&wqkv3, g_wqkv3);
    cudaGetSymbolAddress((void**)&wo3, g_wo3); cudaGetSymbolAddress((void**)&w13, g_w13);
    cudaGetSymbolAddress((void**)&w23, g_w23);

    float* out_x    = (float*)d_out;
    float* out_attn = (float*)d_out + (long)CB * CN * CD;

    const int M = CB * CN;
    const long ND = (long)CN * CD;
    const float inv_sqrt_dh = 0.17677669529663687f;
    const G3 no3 = {nullptr, 0, 0, 0, 0};

    WTab tab;
    int nTiles = 0;
    auto add = [&](int i, const float* src, __nv_bfloat16* dst, int R, int C) {
        tab.e[i] = {src, dst, R, C, (R / 128) * (C / 32)};
        nTiles += tab.e[i].tiles;
    };
    add(0, Wg, wg3, 256, 256);
    for (int l = 0; l < CL; l++) {
        const long w256 = (long)l * 65536, w1k = (long)l * 262144;
        add(1 + l * 6, Wq + w256, wqkv3 + (long)l * 768 * 768, 256, 256);
        add(2 + l * 6, Wk + w256, wqkv3 + (long)l * 768 * 768 + 256 * 768, 256, 256);
        add(3 + l * 6, Wv + w256, wqkv3 + (long)l * 768 * 768 + 512 * 768, 256, 256);
        add(4 + l * 6, Wo + w256, wo3 + (long)l * 256 * 768, 256, 256);
        add(5 + l * 6, W1 + w1k, w13 + (long)l * 1024 * 768, 256, 1024);
        add(6 + l * 6, W2 + w1k, w23 + (long)l * 256 * 3072, 1024, 256);
    }
    wsplit_all<<<nTiles, 256>>>(tab);
    pack_bias<<<CL, 768>>>(bq, bk, bv, bias3);

    embed_kernel<<<M, CD>>>(node, embed, x, x3);

    for (int hop = 0; hop < 2; hop++) {
        launch_gemm(x3, wg3, nullptr, h, M, CD, 768, 768, 768, CD,
                    0, 0, 0, 0, 1, 1.f, 0, 1, 0, no3);
        tsplitB<<<dim3(4, 8, CB), 256>>>(h, h3t, CD, CN, ND, 0, 1, (long)CD * 1536);
        e12_kernel<<<M, CD>>>(h, a1, a2, e1, e2);
        gat_softmax_kernel<<<M, 256>>>(e1, e2, edge, al3);
        G3 gx3 = {x3, (long)CN * 768, 0, 768, 256};
        launch_gemm(al3, h3t, nullptr, x, CN, CD, 1536, 1536, 1536, CD,
                    (long)CN * 1536, (long)CD * 1536, ND, 0, 1, 1.f, 2, CB, 0, gx3);
    }

    scale_pe_kernel<<<M, CD>>>(x, x3);

    for (int l = 0; l < CL; l++) {
        launch_gemm(x3, wqkv3 + (long)l * 768 * 768, bias3 + l * 768, qkv,
                    M, 768, 768, 768, 768, 768,
                    0, 0, 0, 0, 1, 1.f, 0, 1, 0, no3);

        qk_split<<<M, 256>>>(qkv, q3, k3);
        tsplitB<<<dim3(4, 1, CB * CH), 256>>>(qkv + 512, v3t, 768, CN,
                                              (long)CN * 768, 32, CH, 32L * 1536);

        launch_gemm(q3, k3, nullptr, out_attn, CN, CN, 128, 128, 128, CN,
                    (long)CN * 128, (long)CN * 128, (long)CN * CN, 0, 1,
                    inv_sqrt_dh, 0, CB * CH, 0, no3);

        mha_softmax_kernel<<<CB * CH * CN, 256>>>(out_attn, mask, at3);

        G3 go3 = {o3, (long)CN * 768, 32, 768, 256};
        launch_gemm(at3, v3t, nullptr, t, CN, 32, 1536, 1536, 1536, CD,
                    (long)CN * 1536, 32L * 1536, ND, 32, CH, 1.f, 0, CB * CH, 1, go3);

        launch_gemm(o3, wo3 + (long)l * 256 * 768, bo + l * CD, t, M, CD, 768, 768, 768, CD,
                    0, 0, 0, 0, 1, 1.f, 0, 1, 0, no3);
        ln_kernel<<<M, CD>>>(x, t, ln1g + l * CD, ln1b + l * CD, x, x3);

        G3 gff3 = {ff3, 0, 0, 3072, 1024};
        launch_gemm(x3, w13 + (long)l * 1024 * 768, b1 + l * CDFF, ff, M, CDFF, 768, 768, 768, CDFF,
                    0, 0, 0, 0, 1, 1.f, 1, 1, 0, gff3);
        launch_gemm(ff3, w23 + (long)l * 256 * 3072, b2 + l * CD, t, M, CD, 3072, 3072, 3072, CD,
                    0, 0, 0, 0, 1, 1.f, 0, 1, 0, no3);
        const bool last = (l == CL - 1);
        ln_kernel<<<M, CD>>>(x, t, ln2g + l * CD, ln2b + l * CD,
                             last ? out_x : x, last ? nullptr : x3);
    }
}

// round 11
// speedup vs baseline: 1.0897x; 1.0401x over previous
#include <cuda_runtime.h>
#include <cuda_bf16.h>
#include <math.h>
#include <stdint.h>

#define CB 16
#define CN 512
#define CD 256
#define CH 8
#define CDFF 1024
#define CL 2
#define NEG_INF_F (-1e9f)

// ---------------- scratch (dedup'd split tensors: 2 physical segments) ----------------
static __device__ __align__(256) float g_x  [CB*CN*CD];
static __device__ __align__(256) float g_h  [CB*CN*CD];
static __device__ __align__(256) float g_qkv[CB*CN*768];
static __device__ __align__(256) float g_t  [CB*CN*CD];
static __device__ __align__(256) float g_ff [CB*CN*CDFF];
static __device__ __align__(256) float g_e1 [CB*CN];
static __device__ __align__(256) float g_e2 [CB*CN];
static __device__ __align__(256) float g_bias[CL*768];

static __device__ __align__(256) __nv_bfloat16 g_x3  [CB*CN*512];
static __device__ __align__(256) __nv_bfloat16 g_o3  [CB*CN*512];
static __device__ __align__(256) __nv_bfloat16 g_ff3 [CB*CN*2048];
static __device__ __align__(256) __nv_bfloat16 g_h3t [CB*CD*1024];
static __device__ __align__(256) __nv_bfloat16 g_al3 [CB*CN*1024];
static __device__ __align__(256) __nv_bfloat16 g_at3 [CB*CH*CN*1024];
static __device__ __align__(256) __nv_bfloat16 g_q3  [CB*CH*CN*128];
static __device__ __align__(256) __nv_bfloat16 g_k3  [CB*CH*CN*128];
static __device__ __align__(256) __nv_bfloat16 g_v3t [CB*CH*32*1024];
static __device__ __align__(256) __nv_bfloat16 g_wg3 [CD*512];
static __device__ __align__(256) __nv_bfloat16 g_wqkv3[CL*768*512];
static __device__ __align__(256) __nv_bfloat16 g_wo3 [CL*CD*512];
static __device__ __align__(256) __nv_bfloat16 g_w13 [CL*CDFF*512];
static __device__ __align__(256) __nv_bfloat16 g_w23 [CL*CD*2048];

__device__ __forceinline__ __nv_bfloat16 bf_lo(float v) {
    __nv_bfloat16 h = __float2bfloat16(v);
    return __float2bfloat16(v - __bfloat162float(h));
}
__device__ __forceinline__ void cpa16(uint32_t s, const void* g) {
    asm volatile("cp.async.cg.shared.global [%0], [%1], 16;" :: "r"(s), "l"(g));
}
__device__ __forceinline__ void ldsm4(uint32_t& r0, uint32_t& r1, uint32_t& r2, uint32_t& r3, uint32_t addr) {
    asm volatile("ldmatrix.sync.aligned.m8n8.x4.shared.b16 {%0,%1,%2,%3}, [%4];"
                 : "=r"(r0), "=r"(r1), "=r"(r2), "=r"(r3) : "r"(addr));
}

// ---------------- 3-stage cp.async mma.sync bf16 GEMM, chunk-remapped operands ----------------
// Logical K3 = 3S; physical storage 2S. mapA: A-pattern [hi|lo|hi] (phys = k<2S ? k : k-2S).
// mapB: B-pattern [hi|hi|lo] (phys = k<S ? k : k-S). 0 = identity.
template<int BM, int TN>
__global__ __launch_bounds__((BM/32)*(TN/32)*32)
void gemm_mma(const __nv_bfloat16* __restrict__ A, const __nv_bfloat16* __restrict__ B,
              const float* __restrict__ bias, float* __restrict__ C,
              int lda, int ldb, int ldc, int K3, int mapA, int mapB,
              long strA, long strB, long sC1, long sC2, int divC,
              float scale, int act,
              __nv_bfloat16* __restrict__ C3, long sC31, long sC32, int ldc3, int seg3)
{
    constexpr int WM = 32, WN = 32;
    constexpr int BK = 64;
    constexpr int LDS = BK + 8;
    constexpr int MT = 2, NT = 4;
    constexpr int WCOLS = TN / WN;
    constexpr int THREADS = (BM / WM) * (TN / WN) * 32;
    constexpr int AITERS = BM * 8 / THREADS;
    constexpr int BITERS = TN * 8 / THREADS;
    constexpr int STAGES = 3;

    extern __shared__ __nv_bfloat16 smem[];
    __nv_bfloat16* sA = smem;
    __nv_bfloat16* sB = smem + STAGES * BM * LDS;

    const long z = blockIdx.z;
    A += z * strA;
    B += z * strB;
    C += (z / divC) * sC1 + (z % divC) * sC2;
    if (C3) C3 += (z / divC) * sC31 + (z % divC) * sC32;
    const int row0 = blockIdx.y * BM;
    const int col0 = blockIdx.x * TN;

    const int tid = threadIdx.x;
    const int w = tid >> 5, lane = tid & 31;
    const int wr = w / WCOLS, wc = w % WCOLS;
    const int gid = lane >> 2, tig = lane & 3;

    uint32_t sAu = (uint32_t)__cvta_generic_to_shared(sA);
    uint32_t sBu = (uint32_t)__cvta_generic_to_shared(sB);

    const int aRow = lane & 15, aCol = (lane >> 4) << 3;
    const int bRow = ((lane >> 4) << 3) + (lane & 7), bCol = ((lane >> 3) & 1) << 3;

    float acc[MT][NT][4];
#pragma unroll
    for (int mt = 0; mt < MT; mt++)
#pragma unroll
        for (int nt = 0; nt < NT; nt++)
#pragma unroll
            for (int i = 0; i < 4; i++) acc[mt][nt][i] = 0.f;

    const int nChunks = K3 / BK;

    auto issue = [&](int s) {
        const int buf = s % STAGES;
        const int k0 = s * BK;
        const int k0a = mapA ? (k0 < 2 * mapA ? k0 : k0 - 2 * mapA) : k0;
        const int k0b = mapB ? (k0 < mapB ? k0 : k0 - mapB) : k0;
#pragma unroll
        for (int i = 0; i < AITERS; i++) {
            const int idx = i * THREADS + tid;
            const int r = idx >> 3, kc = (idx & 7) * 8;
            cpa16(sAu + (uint32_t)(((buf * BM + r) * LDS + kc) * 2),
                  A + (long)(row0 + r) * lda + k0a + kc);
        }
#pragma unroll
        for (int i = 0; i < BITERS; i++) {
            const int idx = i * THREADS + tid;
            const int r = idx >> 3, kc = (idx & 7) * 8;
            cpa16(sBu + (uint32_t)(((buf * TN + r) * LDS + kc) * 2),
                  B + (long)(col0 + r) * ldb + k0b + kc);
        }
        asm volatile("cp.async.commit_group;");
    };

    issue(0);
    if (nChunks > 1) issue(1);
    for (int c = 0; c < nChunks; c++) {
        if (c + 2 < nChunks) issue(c + 2);
        const int rem = nChunks - 1 - c;
        if (rem >= 2)      asm volatile("cp.async.wait_group 2;");
        else if (rem == 1) asm volatile("cp.async.wait_group 1;");
        else               asm volatile("cp.async.wait_group 0;");
        __syncthreads();

        const int buf = c % STAGES;
        const uint32_t aBase = sAu + (uint32_t)(buf * BM * LDS * 2);
        const uint32_t bBase = sBu + (uint32_t)(buf * TN * LDS * 2);
#pragma unroll
        for (int kk = 0; kk < BK; kk += 16) {
            uint32_t af[MT][4], bfr[NT][2];
#pragma unroll
            for (int mt = 0; mt < MT; mt++) {
                const int r = wr * WM + mt * 16;
                ldsm4(af[mt][0], af[mt][1], af[mt][2], af[mt][3],
                      aBase + (uint32_t)(((r + aRow) * LDS + kk + aCol) * 2));
            }
#pragma unroll
            for (int nt = 0; nt < NT; nt += 2) {
                const int n0 = wc * WN + nt * 8;
                ldsm4(bfr[nt][0], bfr[nt][1], bfr[nt + 1][0], bfr[nt + 1][1],
                      bBase + (uint32_t)(((n0 + bRow) * LDS + kk + bCol) * 2));
            }
#pragma unroll
            for (int mt = 0; mt < MT; mt++)
#pragma unroll
                for (int nt = 0; nt < NT; nt++) {
                    asm volatile(
                        "mma.sync.aligned.m16n8k16.row.col.f32.bf16.bf16.f32 "
                        "{%0,%1,%2,%3}, {%4,%5,%6,%7}, {%8,%9}, {%0,%1,%2,%3};"
                        : "+f"(acc[mt][nt][0]), "+f"(acc[mt][nt][1]),
                          "+f"(acc[mt][nt][2]), "+f"(acc[mt][nt][3])
                        : "r"(af[mt][0]), "r"(af[mt][1]), "r"(af[mt][2]), "r"(af[mt][3]),
                          "r"(bfr[nt][0]), "r"(bfr[nt][1]));
                }
        }
        __syncthreads();
    }

    // epilogue: fp32 C + optional dedup'd bf16 split C3 (hi at base, lo at base+seg3)
#pragma unroll
    for (int mt = 0; mt < MT; mt++) {
#pragma unroll
        for (int nt = 0; nt < NT; nt++) {
            const int rloc = wr * WM + mt * 16 + gid;
            const int cloc = wc * WN + nt * 8 + tig * 2;
            const int cg = col0 + cloc;
            float b0 = bias ? bias[cg] : 0.f;
            float b1 = bias ? bias[cg + 1] : 0.f;
#pragma unroll
            for (int half = 0; half < 2; half++) {
                const int rg = row0 + rloc + half * 8;
                float v0 = acc[mt][nt][half * 2 + 0] * scale + b0;
                float v1 = acc[mt][nt][half * 2 + 1] * scale + b1;
                if (act == 1) { v0 = fmaxf(v0, 0.f); v1 = fmaxf(v1, 0.f); }
                else if (act == 2) {
                    v0 = (v0 > 0.f) ? v0 : expm1f(v0);
                    v1 = (v1 > 0.f) ? v1 : expm1f(v1);
                }
                *reinterpret_cast<float2*>(&C[(long)rg * ldc + cg]) = make_float2(v0, v1);
                if (C3) {
                    __nv_bfloat16 h0 = __float2bfloat16(v0);
                    __nv_bfloat16 h1 = __float2bfloat16(v1);
                    long base = (long)rg * ldc3 + cg;
                    *reinterpret_cast<__nv_bfloat162*>(&C3[base]) = __nv_bfloat162(h0, h1);
                    *reinterpret_cast<__nv_bfloat162*>(&C3[base + seg3]) =
                        __nv_bfloat162(bf_lo(v0), bf_lo(v1));
                }
            }
        }
    }
}

// ---------------- fused weight split: src [R,C] fp32 -> dst [C, 2R] bf16 [hi|lo] ----------------
struct WEnt { const float* src; __nv_bfloat16* dst; int R; int C; int tiles; };
struct WTab { WEnt e[13]; };

__global__ void wsplit_all(WTab tab)
{
    __shared__ float tile[128][33];
    int bid = blockIdx.x;
    int i = 0;
    while (bid >= tab.e[i].tiles) { bid -= tab.e[i].tiles; i++; }
    const float* in = tab.e[i].src;
    __nv_bfloat16* out = tab.e[i].dst;
    const int R = tab.e[i].R, C = tab.e[i].C;
    const int tC = C >> 5;
    const int r0 = (bid / tC) * 128, c0 = (bid % tC) * 32;

    for (int t = threadIdx.x; t < 128 * 32; t += 256) {
        int rr = t >> 5, cc = t & 31;
        tile[rr][cc] = in[(long)(r0 + rr) * C + c0 + cc];
    }
    __syncthreads();
    for (int t = threadIdx.x; t < 32 * 128; t += 256) {
        int cc = t >> 7, rr = t & 127;
        float v = tile[rr][cc];
        long ob = (long)(c0 + cc) * (2L * R) + (r0 + rr);
        out[ob] = __float2bfloat16(v);
        out[ob + R] = bf_lo(v);
    }
}

__global__ void pack_bias(const float* __restrict__ bq, const float* __restrict__ bk,
                          const float* __restrict__ bv, float* __restrict__ dst)
{
    const int l = blockIdx.x;
    const int d = threadIdx.x;
    float v;
    if (d < 256) v = bq[l * 256 + d];
    else if (d < 512) v = bk[l * 256 + d - 256];
    else v = bv[l * 256 + d - 512];
    dst[l * 768 + d] = v;
}

// ---------------- elementwise kernels ----------------

__global__ void embed_kernel(const int* __restrict__ node, const float* __restrict__ embed,
                             float* __restrict__ x, __nv_bfloat16* __restrict__ x3)
{
    const int row = blockIdx.x;
    const int d = threadIdx.x;
    const float v = embed[(long)node[row] * CD + d];
    x[(long)row * CD + d] = v;
    x3[(long)row * 512 + d] = __float2bfloat16(v);
    x3[(long)row * 512 + 256 + d] = bf_lo(v);
}

// data transpose-split: in [R,C] -> out [C, 2R] [hi|lo]
__global__ void tsplitB(const float* __restrict__ in, __nv_bfloat16* __restrict__ out,
                        int irs, int R, long sIn1, long sIn2, int divIn, long sOut)
{
    __shared__ float tile[128][33];
    const long z = blockIdx.z;
    in  += (z / divIn) * sIn1 + (z % divIn) * sIn2;
    out += z * sOut;
    const int r0 = blockIdx.x * 128, c0 = blockIdx.y * 32;
    for (int i = threadIdx.x; i < 128 * 32; i += 256) {
        int rr = i >> 5, cc = i & 31;
        tile[rr][cc] = in[(long)(r0 + rr) * irs + c0 + cc];
    }
    __syncthreads();
    for (int i = threadIdx.x; i < 32 * 128; i += 256) {
        int cc = i >> 7, rr = i & 127;
        float v = tile[rr][cc];
        long ob = (long)(c0 + cc) * (2L * R) + (r0 + rr);
        out[ob] = __float2bfloat16(v);
        out[ob + R] = bf_lo(v);
    }
}

__global__ void qk_split(const float* __restrict__ qkv,
                         __nv_bfloat16* __restrict__ q3, __nv_bfloat16* __restrict__ k3)
{
    const int row = blockIdx.x;
    const int b = row >> 9, i = row & 511;
    const int d = threadIdx.x;
    const int h = d >> 5, dd = d & 31;
    const long base = ((long)(b * CH + h) * CN + i) * 128;
    const __nv_bfloat16 zero = __float2bfloat16(0.f);
    float qv = qkv[(long)row * 768 + d];
    float kv = qkv[(long)row * 768 + 256 + d];
    __nv_bfloat16 qh = __float2bfloat16(qv);
    __nv_bfloat16 ql = bf_lo(qv);
    __nv_bfloat16 kh = __float2bfloat16(kv);
    __nv_bfloat16 kl = bf_lo(kv);
    q3[base + dd] = qh;  q3[base + 32 + dd] = ql; q3[base + 64 + dd] = qh; q3[base + 96 + dd] = zero;
    k3[base + dd] = kh;  k3[base + 32 + dd] = kh; k3[base + 64 + dd] = kl; k3[base + 96 + dd] = zero;
}

__global__ void e12_kernel(const float* __restrict__ h, const float* __restrict__ a1,
                           const float* __restrict__ a2, float* __restrict__ e1, float* __restrict__ e2)
{
    const int row = blockIdx.x;
    const int d = threadIdx.x;
    __shared__ float s1[256], s2[256];
    const float hv = h[(long)row * CD + d];
    s1[d] = hv * a1[d];
    s2[d] = hv * a2[d];
    __syncthreads();
    for (int off = 128; off > 0; off >>= 1) {
        if (d < off) { s1[d] += s1[d + off]; s2[d] += s2[d + off]; }
        __syncthreads();
    }
    if (d == 0) { e1[row] = s1[0]; e2[row] = s2[0]; }
}

__global__ void gat_softmax_kernel(const float* __restrict__ e1, const float* __restrict__ e2,
                                   const int* __restrict__ edge, __nv_bfloat16* __restrict__ al3)
{
    const int row = blockIdx.x;
    const int b = row / CN;
    const int t = threadIdx.x;
    __shared__ float red[256];
    const float ei = e1[row];
    float vals[2];
#pragma unroll
    for (int p = 0; p < 2; p++) {
        const int j = t + p * 256;
        float e = ei + e2[b * CN + j];
        e = (e >= 0.f) ? e : 0.2f * e;
        vals[p] = (edge[(long)row * CN + j] > 0) ? e : NEG_INF_F;
    }
    red[t] = fmaxf(vals[0], vals[1]);
    __syncthreads();
    for (int off = 128; off > 0; off >>= 1) { if (t < off) red[t] = fmaxf(red[t], red[t + off]); __syncthreads(); }
    const float m = red[0];
    __syncthreads();
    float ex[2] = {__expf(vals[0] - m), __expf(vals[1] - m)};
    red[t] = ex[0] + ex[1];
    __syncthreads();
    for (int off = 128; off > 0; off >>= 1) { if (t < off) red[t] += red[t + off]; __syncthreads(); }
    const float inv = 1.f / red[0];
    const long b3 = (long)row * 1024;
#pragma unroll
    for (int p = 0; p < 2; p++) {
        const int j = t + p * 256;
        const float pr = ex[p] * inv;
        al3[b3 + j] = __float2bfloat16(pr);
        al3[b3 + 512 + j] = bf_lo(pr);
    }
}

__global__ void mha_softmax_kernel(float* __restrict__ s, const int* __restrict__ mask,
                                   __nv_bfloat16* __restrict__ at3, int writeProbs)
{
    const int r = blockIdx.x;
    const int b = r / (CH * CN);
    const int t = threadIdx.x;
    __shared__ float red[256];
    float* srow = s + (long)r * CN;
    float vals[2];
#pragma unroll
    for (int p = 0; p < 2; p++) {
        const int j = t + p * 256;
        vals[p] = srow[j] + (float)mask[b * CN + j] * NEG_INF_F;
    }
    red[t] = fmaxf(vals[0], vals[1]);
    __syncthreads();
    for (int off = 128; off > 0; off >>= 1) { if (t < off) red[t] = fmaxf(red[t], red[t + off]); __syncthreads(); }
    const float m = red[0];
    __syncthreads();
    float ex[2] = {__expf(vals[0] - m), __expf(vals[1] - m)};
    red[t] = ex[0] + ex[1];
    __syncthreads();
    for (int off = 128; off > 0; off >>= 1) { if (t < off) red[t] += red[t + off]; __syncthreads(); }
    const float inv = 1.f / red[0];
    const long b3 = (long)r * 1024;
#pragma unroll
    for (int p = 0; p < 2; p++) {
        const int j = t + p * 256;
        const float pr = ex[p] * inv;
        if (writeProbs) srow[j] = pr;
        at3[b3 + j] = __float2bfloat16(pr);
        at3[b3 + 512 + j] = bf_lo(pr);
    }
}

__global__ void scale_pe_kernel(float* __restrict__ x, __nv_bfloat16* __restrict__ x3)
{
    const int row = blockIdx.x;
    const int n = row % CN;
    const int d = threadIdx.x;
    const float expo = (2.0f * (float)(d >> 1)) / (float)CD;
    const float angle = (float)n * powf(10000.0f, -expo);
    const float pe = (d & 1) ? cosf(angle) : sinf(angle);
    const long idx = (long)row * CD + d;
    const float v = x[idx] * 16.0f + pe;
    x[idx] = v;
    x3[(long)row * 512 + d] = __float2bfloat16(v);
    x3[(long)row * 512 + 256 + d] = bf_lo(v);
}

__global__ void ln_kernel(const float* __restrict__ x, const float* __restrict__ delta,
                          const float* __restrict__ g, const float* __restrict__ bb,
                          float* __restrict__ out, __nv_bfloat16* __restrict__ x3)
{
    const int row = blockIdx.x;
    const int d = threadIdx.x;
    __shared__ float red[256];
    const long idx = (long)row * CD + d;
    const float v = x[idx] + delta[idx];
    red[d] = v;
    __syncthreads();
    for (int off = 128; off > 0; off >>= 1) { if (d < off) red[d] += red[d + off]; __syncthreads(); }
    const float mu = red[0] * (1.0f / CD);
    __syncthreads();
    const float c = v - mu;
    red[d] = c * c;
    __syncthreads();
    for (int off = 128; off > 0; off >>= 1) { if (d < off) red[d] += red[d + off]; __syncthreads(); }
    const float var = red[0] * (1.0f / CD);
    const float r = c * rsqrtf(var + 1e-6f) * g[d] + bb[d];
    out[idx] = r;
    if (x3) {
        x3[(long)row * 512 + d] = __float2bfloat16(r);
        x3[(long)row * 512 + 256 + d] = bf_lo(r);
    }
}

// ---------------- host ----------------
struct G3 { __nv_bfloat16* p; long s1; long s2; int ld; int seg; };

// cfg 0: BM=64 TN=64 (128 thr); cfg 1: BM=64 TN=32 (64 thr)
static void launch_gemm(const __nv_bfloat16* A, const __nv_bfloat16* B, const float* bias, float* C,
                        int M, int N, int K3, int lda, int ldb, int ldc, int mapA, int mapB,
                        long sA, long sB, long sC1, long sC2, int divC,
                        float scale, int act, int batch, int cfg, G3 g3)
{
    if (cfg == 0) {
        dim3 g(N / 64, M / 64, batch);
        size_t sm = 3 * (64 + 64) * 72 * 2;
        gemm_mma<64, 64><<<g, 128, sm>>>(A, B, bias, C, lda, ldb, ldc, K3, mapA, mapB,
            sA, sB, sC1, sC2, divC, scale, act, g3.p, g3.s1, g3.s2, g3.ld, g3.seg);
    } else {
        dim3 g(N / 32, M / 64, batch);
        size_t sm = 3 * (64 + 32) * 72 * 2;
        gemm_mma<64, 32><<<g, 64, sm>>>(A, B, bias, C, lda, ldb, ldc, K3, mapA, mapB,
            sA, sB, sC1, sC2, divC, scale, act, g3.p, g3.s1, g3.s2, g3.ld, g3.seg);
    }
}

extern "C" void kernel_launch(void* const* d_in, const int* in_sizes, int n_in,
                              void* d_out, int out_size)
{
    const int*   node  = (const int*)  d_in[0];
    const int*   edge  = (const int*)  d_in[1];
    const int*   mask  = (const int*)  d_in[2];
    const float* embed = (const float*)d_in[4];
    const float* Wg    = (const float*)d_in[5];
    const float* a1    = (const float*)d_in[6];
    const float* a2    = (const float*)d_in[7];
    const float* Wq    = (const float*)d_in[8];
    const float* bq    = (const float*)d_in[9];
    const float* Wk    = (const float*)d_in[10];
    const float* bk    = (const float*)d_in[11];
    const float* Wv    = (const float*)d_in[12];
    const float* bv    = (const float*)d_in[13];
    const float* Wo    = (const float*)d_in[14];
    const float* bo    = (const float*)d_in[15];
    const float* W1    = (const float*)d_in[16];
    const float* b1    = (const float*)d_in[17];
    const float* W2    = (const float*)d_in[18];
    const float* b2    = (const float*)d_in[19];
    const float* ln1g  = (const float*)d_in[20];
    const float* ln1b  = (const float*)d_in[21];
    const float* ln2g  = (const float*)d_in[22];
    const float* ln2b  = (const float*)d_in[23];

    cudaFuncSetAttribute((const void*)gemm_mma<64,64>, cudaFuncAttributeMaxDynamicSharedMemorySize, 60000);
    cudaFuncSetAttribute((const void*)gemm_mma<64,32>, cudaFuncAttributeMaxDynamicSharedMemorySize, 45000);

    float *x, *h, *qkv, *t, *ff, *e1, *e2, *bias3;
    __nv_bfloat16 *x3, *o3, *ff3, *h3t, *al3, *at3, *q3, *k3, *v3t;
    __nv_bfloat16 *wg3, *wqkv3, *wo3, *w13, *w23;
    cudaGetSymbolAddress((void**)&x, g_x);     cudaGetSymbolAddress((void**)&h, g_h);
    cudaGetSymbolAddress((void**)&qkv, g_qkv); cudaGetSymbolAddress((void**)&t, g_t);
    cudaGetSymbolAddress((void**)&ff, g_ff);
    cudaGetSymbolAddress((void**)&e1, g_e1);   cudaGetSymbolAddress((void**)&e2, g_e2);
    cudaGetSymbolAddress((void**)&bias3, g_bias);
    cudaGetSymbolAddress((void**)&x3, g_x3);   cudaGetSymbolAddress((void**)&o3, g_o3);
    cudaGetSymbolAddress((void**)&ff3, g_ff3); cudaGetSymbolAddress((void**)&h3t, g_h3t);
    cudaGetSymbolAddress((void**)&al3, g_al3); cudaGetSymbolAddress((void**)&at3, g_at3);
    cudaGetSymbolAddress((void**)&q3, g_q3);   cudaGetSymbolAddress((void**)&k3, g_k3);
    cudaGetSymbolAddress((void**)&v3t, g_v3t);
    cudaGetSymbolAddress((void**)&wg3, g_wg3); cudaGetSymbolAddress((void**)&wqkv3, g_wqkv3);
    cudaGetSymbolAddress((void**)&wo3, g_wo3); cudaGetSymbolAddress((void**)&w13, g_w13);
    cudaGetSymbolAddress((void**)&w23, g_w23);

    float* out_x    = (float*)d_out;
    float* out_attn = (float*)d_out + (long)CB * CN * CD;

    const int M = CB * CN;
    const long ND = (long)CN * CD;
    const float inv_sqrt_dh = 0.17677669529663687f;
    const G3 no3 = {nullptr, 0, 0, 0, 0};

    WTab tab;
    int nTiles = 0;
    auto add = [&](int i, const float* src, __nv_bfloat16* dst, int R, int C) {
        tab.e[i] = {src, dst, R, C, (R / 128) * (C / 32)};
        nTiles += tab.e[i].tiles;
    };
    add(0, Wg, wg3, 256, 256);
    for (int l = 0; l < CL; l++) {
        const long w256 = (long)l * 65536, w1k = (long)l * 262144;
        add(1 + l * 6, Wq + w256, wqkv3 + (long)l * 768 * 512, 256, 256);
        add(2 + l * 6, Wk + w256, wqkv3 + (long)l * 768 * 512 + 256 * 512, 256, 256);
        add(3 + l * 6, Wv + w256, wqkv3 + (long)l * 768 * 512 + 512 * 512, 256, 256);
        add(4 + l * 6, Wo + w256, wo3 + (long)l * 256 * 512, 256, 256);
        add(5 + l * 6, W1 + w1k, w13 + (long)l * 1024 * 512, 256, 1024);
        add(6 + l * 6, W2 + w1k, w23 + (long)l * 256 * 2048, 1024, 256);
    }
    wsplit_all<<<nTiles, 256>>>(tab);
    pack_bias<<<CL, 768>>>(bq, bk, bv, bias3);

    embed_kernel<<<M, CD>>>(node, embed, x, x3);

    for (int hop = 0; hop < 2; hop++) {
        // h = x @ Wg  (A: x3 [hi|lo] S=256; B: wg3 [hi|lo] S=256)
        launch_gemm(x3, wg3, nullptr, h, M, CD, 768, 512, 512, CD, 256, 256,
                    0, 0, 0, 0, 1, 1.f, 0, 1, 0, no3);
        tsplitB<<<dim3(4, 8, CB), 256>>>(h, h3t, CD, CN, ND, 0, 1, (long)CD * 1024);
        e12_kernel<<<M, CD>>>(h, a1, a2, e1, e2);
        gat_softmax_kernel<<<M, 256>>>(e1, e2, edge, al3);
        // x = elu(alpha@h), emit x3
        G3 gx3 = {x3, (long)CN * 512, 0, 512, 256};
        launch_gemm(al3, h3t, nullptr, x, CN, CD, 1536, 1024, 1024, CD, 512, 512,
                    (long)CN * 1024, (long)CD * 1024, ND, 0, 1, 1.f, 2, CB, 0, gx3);
    }

    scale_pe_kernel<<<M, CD>>>(x, x3);

    for (int l = 0; l < CL; l++) {
        launch_gemm(x3, wqkv3 + (long)l * 768 * 512, bias3 + l * 768, qkv,
                    M, 768, 768, 512, 512, 768, 256, 256,
                    0, 0, 0, 0, 1, 1.f, 0, 1, 0, no3);

        qk_split<<<M, 256>>>(qkv, q3, k3);
        tsplitB<<<dim3(4, 1, CB * CH), 256>>>(qkv + 512, v3t, 768, CN,
                                              (long)CN * 768, 32, CH, 32L * 1024);

        launch_gemm(q3, k3, nullptr, out_attn, CN, CN, 128, 128, 128, CN, 0, 0,
                    (long)CN * 128, (long)CN * 128, (long)CN * CN, 0, 1,
                    inv_sqrt_dh, 0, CB * CH, 0, no3);

        mha_softmax_kernel<<<CB * CH * CN, 256>>>(out_attn, mask, at3, l == CL - 1 ? 1 : 0);

        // o = attn@v (A: at3 S=512; B: v3t S=512), emit o3
        G3 go3 = {o3, (long)CN * 512, 32, 512, 256};
        launch_gemm(at3, v3t, nullptr, t, CN, 32, 1536, 1024, 1024, CD, 512, 512,
                    (long)CN * 1024, 32L * 1024, ND, 32, CH, 1.f, 0, CB * CH, 1, go3);

        launch_gemm(o3, wo3 + (long)l * 256 * 512, bo + l * CD, t, M, CD, 768,
                    512, 512, CD, 256, 256,
                    0, 0, 0, 0, 1, 1.f, 0, 1, 0, no3);
        ln_kernel<<<M, CD>>>(x, t, ln1g + l * CD, ln1b + l * CD, x, x3);

        G3 gff3 = {ff3, 0, 0, 2048, 1024};
        launch_gemm(x3, w13 + (long)l * 1024 * 512, b1 + l * CDFF, ff, M, CDFF, 768,
                    512, 512, CDFF, 256, 256,
                    0, 0, 0, 0, 1, 1.f, 1, 1, 0, gff3);
        launch_gemm(ff3, w23 + (long)l * 256 * 2048, b2 + l * CD, t, M, CD, 3072,
                    2048, 2048, CD, 1024, 1024,
                    0, 0, 0, 0, 1, 1.f, 0, 1, 0, no3);
        const bool last = (l == CL - 1);
        ln_kernel<<<M, CD>>>(x, t, ln2g + l * CD, ln2b + l * CD,
                             last ? out_x : x, last ? nullptr : x3);
    }
}